// round 8
// baseline (speedup 1.0000x reference)
#include <cuda_runtime.h>

#define LROW 16384
#define N1 8199
#define N2 4107
#define N3 2061
#define N4 1038
#define ROWS_MAX 2048

// global scratch row strides (floats, multiples of 4)
#define S1   8200
#define S1EO 8208      // split a1: e at +0 (4100 used), o at +4104 (4099 used)
#define A1O  4104
#define S2   4112
#define S3   2064
#define S4   1040

__device__ float g_a1[(size_t)ROWS_MAX * S1EO];   // split a1 (e|o)
__device__ float g_d1[(size_t)ROWS_MAX * S1];
__device__ float g_d2[(size_t)ROWS_MAX * S2];
__device__ float g_d3[(size_t)ROWS_MAX * S3];
__device__ float g_d4[(size_t)ROWS_MAX * S4];
__device__ float g_a4[(size_t)ROWS_MAX * S4];
__device__ float g_thr[ROWS_MAX];

#define HLIT { \
    0.05441584224308161f,    0.3128715909144659f,    0.6756307362980128f, \
    0.5853546836548691f,    -0.015829105256023893f, -0.2840155429624281f, \
    0.00047248457399797254f, 0.128747426620186f,    -0.01736930100202211f, \
   -0.04408825393106472f,    0.013981027917015516f,  0.008746094047015655f, \
   -0.00487035299301066f,   -0.0003917403729959771f, 0.0006754494059985568f, \
   -0.00011747678400228192f }

__device__ __forceinline__ float softthr(float v, float thr) {
    float av = fabsf(v) - thr;
    return av > 0.f ? copysignf(av, v) : 0.f;
}

// polyphase DWT: 4 outputs from e[12], o[12] where e[j] = ae[m0-8+j] (K3 form)
// or e[j] = xe[dk+j] (K1 form, off=0 vs off=1)
template <int OFF>
__device__ __forceinline__ void dwt4_eo(const float* e, const float* o,
                                        float* ca, float* cd)
{
    const float H[16] = HLIT;
    #pragma unroll
    for (int r = 0; r < 4; r++) {
        float a = 0.f, d = 0.f;
        #pragma unroll
        for (int s = 0; s < 8; s++) {
            float ev = e[r + s + OFF], ov = o[r + s + OFF];
            a = fmaf(H[2 * s],      ev, a);
            a = fmaf(H[2 * s + 1],  ov, a);
            d = fmaf(H[15 - 2 * s], ev, d);
            d = fmaf(-H[14 - 2 * s], ov, d);
        }
        ca[r] = a; cd[r] = d;
    }
}

// scalar DWT output k from a raw accessor (reflect handled by caller lambda-ish)
__device__ __forceinline__ float2 dwt1_scalar_global(const float* __restrict__ xin,
                                                     int n, int k)
{
    const float H[16] = HLIT;
    float a = 0.f, d = 0.f;
    #pragma unroll
    for (int t = 0; t < 16; t++) {
        int m = 2 * k + t - 14;
        m = (m < 0) ? (-1 - m) : m;
        m = (m >= n) ? (2 * n - 1 - m) : m;
        float xv = xin[m];
        a = fmaf(H[t], xv, a);
        d = fmaf((t & 1) ? -H[15 - t] : H[15 - t], xv, d);
    }
    return make_float2(a, d);
}

// split-array accessor with reflect
__device__ __forceinline__ float getA(const float* __restrict__ ae,
                                      const float* __restrict__ ao,
                                      int j, int n)
{
    j = (j < 0) ? (-1 - j) : j;
    j = (j >= n) ? (2 * n - 1 - j) : j;
    return (j & 1) ? ao[j >> 1] : ae[j >> 1];
}

__device__ __forceinline__ float2 dwt_scalar_eo(const float* __restrict__ ae,
                                                const float* __restrict__ ao,
                                                int n, int k)
{
    const float H[16] = HLIT;
    float a = 0.f, d = 0.f;
    #pragma unroll
    for (int t = 0; t < 16; t++) {
        float xv = getA(ae, ao, 2 * k + t - 14, n);
        a = fmaf(H[t], xv, a);
        d = fmaf((t & 1) ? -H[15 - t] : H[15 - t], xv, d);
    }
    return make_float2(a, d);
}

// ===================== K1: streaming level-1 DWT (4 blocks x 2048 outputs/row) ==
__global__ void __launch_bounds__(256, 4)
k_dwt1(const float* __restrict__ x, float* __restrict__ a1g,
       float* __restrict__ d1g)
{
    __shared__ alignas(16) float xe[2058];
    __shared__ alignas(16) float xo[2058];

    const int tid = threadIdx.x;
    const int bx  = blockIdx.x;           // 0..3
    const int row = blockIdx.y;
    const int k0  = 2048 * bx;
    const float* xin = x + (size_t)row * LROW;
    float* pae = a1g + (size_t)row * S1EO;
    float* pao = pae + A1O;
    float* pd1 = d1g + (size_t)row * S1;

    // ---- stage + deinterleave x[2k0-14 .. 2k0+4102) into xe/xo ----
    const int base    = 2 * k0 - 14;
    const int base_al = base - 2;         // 16B aligned
    for (int q = tid; q < 1030; q += 256) {
        int g = base_al + 4 * q;
        float v0, v1, v2, v3;
        if (g >= 0 && g + 4 <= LROW) {
            float4 t4 = *reinterpret_cast<const float4*>(xin + g);
            v0 = t4.x; v1 = t4.y; v2 = t4.z; v3 = t4.w;
        } else {
            int m0 = g;     m0 = (m0 < 0) ? (-1 - m0) : ((m0 >= LROW) ? 2*LROW-1-m0 : m0);
            int m1 = g + 1; m1 = (m1 < 0) ? (-1 - m1) : ((m1 >= LROW) ? 2*LROW-1-m1 : m1);
            int m2 = g + 2; m2 = (m2 < 0) ? (-1 - m2) : ((m2 >= LROW) ? 2*LROW-1-m2 : m2);
            int m3 = g + 3; m3 = (m3 < 0) ? (-1 - m3) : ((m3 >= LROW) ? 2*LROW-1-m3 : m3);
            v0 = xin[m0]; v1 = xin[m1]; v2 = xin[m2]; v3 = xin[m3];
        }
        int h = 2 * q - 1;                 // element rel = 4q-2 → xe idx 2q-1
        if (h >= 0)       { xe[h] = v0;     xo[h] = v1; }
        if (h + 1 < 2058) { xe[h + 1] = v2; xo[h + 1] = v3; }
    }
    __syncthreads();

    // ---- 8 outputs/thread via 2 chunks of 4; halo already reflected in smem ----
    #pragma unroll
    for (int c = 0; c < 2; c++) {
        int dk = 1024 * c + 4 * tid;       // output k = k0 + dk
        float e[12], o[12];
        #pragma unroll
        for (int j = 0; j < 3; j++) {
            float4 ve = *reinterpret_cast<const float4*>(xe + dk + 4 * j);
            float4 vo = *reinterpret_cast<const float4*>(xo + dk + 4 * j);
            e[4*j]=ve.x; e[4*j+1]=ve.y; e[4*j+2]=ve.z; e[4*j+3]=ve.w;
            o[4*j]=vo.x; o[4*j+1]=vo.y; o[4*j+2]=vo.z; o[4*j+3]=vo.w;
        }
        float ca[4], cd[4];
        dwt4_eo<0>(e, o, ca, cd);
        int k = k0 + dk;
        *reinterpret_cast<float4*>(pd1 + k) = make_float4(cd[0], cd[1], cd[2], cd[3]);
        *reinterpret_cast<float2*>(pae + (k >> 1)) = make_float2(ca[0], ca[2]);
        *reinterpret_cast<float2*>(pao + (k >> 1)) = make_float2(ca[1], ca[3]);
    }
    // tail k = 8192..8198 (only block bx==3)
    if (bx == 3 && tid < 7) {
        int k = 8192 + tid;
        float2 ad = dwt1_scalar_global(xin, LROW, k);
        pd1[k] = ad.y;
        if (k & 1) pao[k >> 1] = ad.x; else pae[k >> 1] = ad.x;
    }
}

// ===================== K2: per-row exact median of |d1| -> thr ================
__global__ void __launch_bounds__(256, 4)
k_med(const float* __restrict__ d1g, float* __restrict__ thr_out)
{
    __shared__ int      s_hist[4][256];
    __shared__ unsigned s_pref;
    __shared__ int      s_rank;

    const int tid = threadIdx.x, lane = tid & 31, warp = tid >> 5;
    const float* pd = d1g + (size_t)blockIdx.x * S1;

    #pragma unroll
    for (int rr = 0; rr < 4; rr++) s_hist[rr][tid] = 0;
    if (tid == 0) { s_pref = 0u; s_rank = (N1 - 1) / 2; }

    float dreg[32];
    #pragma unroll
    for (int c = 0; c < 8; c++) {
        float4 v = *reinterpret_cast<const float4*>(pd + 1024 * c + 4 * tid);
        dreg[4*c] = v.x; dreg[4*c+1] = v.y; dreg[4*c+2] = v.z; dreg[4*c+3] = v.w;
    }
    float dtail = (tid < 7) ? pd[8192 + tid] : 0.f;
    __syncthreads();

    for (int b3 = 3; b3 >= 0; --b3) {
        const unsigned pref = s_pref;
        const int rank = s_rank;
        const int sh = b3 * 8;
        int* hist = s_hist[b3];
        #pragma unroll
        for (int j = 0; j < 32; j++) {
            unsigned u = __float_as_uint(fabsf(dreg[j]));
            bool mt = (b3 == 3) || ((u >> (sh + 8)) == pref);
            if (__any_sync(0xffffffffu, mt)) {
                unsigned bin = (u >> sh) & 255u;
                unsigned key = mt ? bin : 256u;
                unsigned grp = __match_any_sync(0xffffffffu, key);
                if (mt && lane == (__ffs(grp) - 1))
                    atomicAdd(&hist[bin], __popc(grp));
            }
        }
        if (tid < 7) {
            unsigned u = __float_as_uint(fabsf(dtail));
            if ((b3 == 3) || ((u >> (sh + 8)) == pref))
                atomicAdd(&hist[(u >> sh) & 255u], 1);
        }
        __syncthreads();
        if (warp == 0) {
            int base = lane * 8;
            int cnt[8], s = 0;
            #pragma unroll
            for (int q = 0; q < 8; q++) { cnt[q] = hist[base + q]; s += cnt[q]; }
            int incl = s;
            #pragma unroll
            for (int o = 1; o < 32; o <<= 1) {
                int t2 = __shfl_up_sync(0xffffffffu, incl, o);
                if (lane >= o) incl += t2;
            }
            int excl = incl - s;
            if (rank >= excl && rank < incl) {
                int acc = excl;
                #pragma unroll
                for (int q = 0; q < 8; q++) {
                    if (rank < acc + cnt[q]) {
                        s_pref = (pref << 8) | (unsigned)(base + q);
                        s_rank = rank - acc;
                        break;
                    }
                    acc += cnt[q];
                }
            }
        }
        __syncthreads();
    }
    if (tid == 0) {
        float med = __uint_as_float(s_pref);
        thr_out[blockIdx.x] = (med / 0.6745f) * 4.4054649f;  // * sqrt(2 ln 16384)
    }
}

// ===================== K3: fused DWT levels 2-4 (block per row, polyphase) =====
__global__ void __launch_bounds__(256, 4)
k_dwt234(const float* __restrict__ a1g, float* __restrict__ d2g,
         float* __restrict__ d3g, float* __restrict__ d4g,
         float* __restrict__ a4g)
{
    __shared__ alignas(16) float a2e[2056], a2o[2056];
    __shared__ alignas(16) float a3e[1032], a3o[1032];

    const int tid = threadIdx.x;
    const int row = blockIdx.x;
    const float* pae = a1g + (size_t)row * S1EO;
    const float* pao = pae + A1O;
    float* pd2 = d2g + (size_t)row * S2;
    float* pd3 = d3g + (size_t)row * S3;
    float* pd4 = d4g + (size_t)row * S4;
    float* pa4 = a4g + (size_t)row * S4;

    // ---- level 2: global split a1 -> smem split a2 + d2 global ----
    #pragma unroll
    for (int c = 0; c < 4; c++) {
        int m0 = 1024 * c + 4 * tid;       // < 4096
        if (m0 >= 8) {
            float e[12], o[12];
            #pragma unroll
            for (int j = 0; j < 3; j++) {
                float4 ve = *reinterpret_cast<const float4*>(pae + m0 - 8 + 4 * j);
                float4 vo = *reinterpret_cast<const float4*>(pao + m0 - 8 + 4 * j);
                e[4*j]=ve.x; e[4*j+1]=ve.y; e[4*j+2]=ve.z; e[4*j+3]=ve.w;
                o[4*j]=vo.x; o[4*j+1]=vo.y; o[4*j+2]=vo.z; o[4*j+3]=vo.w;
            }
            float ca[4], cd[4];
            dwt4_eo<1>(e, o, ca, cd);
            *reinterpret_cast<float4*>(pd2 + m0) = make_float4(cd[0], cd[1], cd[2], cd[3]);
            *reinterpret_cast<float2*>(a2e + (m0 >> 1)) = make_float2(ca[0], ca[2]);
            *reinterpret_cast<float2*>(a2o + (m0 >> 1)) = make_float2(ca[1], ca[3]);
        } else {
            #pragma unroll
            for (int r = 0; r < 4; r++) {
                int m = m0 + r;
                float2 ad = dwt_scalar_eo(pae, pao, N1, m);
                pd2[m] = ad.y;
                if (m & 1) a2o[m >> 1] = ad.x; else a2e[m >> 1] = ad.x;
            }
        }
    }
    {   // tail m = 4096..4106
        int m = 4096 + tid;
        if (m < N2) {
            float2 ad = dwt_scalar_eo(pae, pao, N1, m);
            pd2[m] = ad.y;
            if (m & 1) a2o[m >> 1] = ad.x; else a2e[m >> 1] = ad.x;
        }
    }
    __syncthreads();

    // ---- level 3: smem split a2 -> smem split a3 + d3 global ----
    #pragma unroll
    for (int c = 0; c < 2; c++) {
        int m0 = 1024 * c + 4 * tid;       // < 2048
        if (m0 >= 8) {
            float e[12], o[12];
            #pragma unroll
            for (int j = 0; j < 3; j++) {
                float4 ve = *reinterpret_cast<const float4*>(a2e + m0 - 8 + 4 * j);
                float4 vo = *reinterpret_cast<const float4*>(a2o + m0 - 8 + 4 * j);
                e[4*j]=ve.x; e[4*j+1]=ve.y; e[4*j+2]=ve.z; e[4*j+3]=ve.w;
                o[4*j]=vo.x; o[4*j+1]=vo.y; o[4*j+2]=vo.z; o[4*j+3]=vo.w;
            }
            float ca[4], cd[4];
            dwt4_eo<1>(e, o, ca, cd);
            *reinterpret_cast<float4*>(pd3 + m0) = make_float4(cd[0], cd[1], cd[2], cd[3]);
            *reinterpret_cast<float2*>(a3e + (m0 >> 1)) = make_float2(ca[0], ca[2]);
            *reinterpret_cast<float2*>(a3o + (m0 >> 1)) = make_float2(ca[1], ca[3]);
        } else {
            #pragma unroll
            for (int r = 0; r < 4; r++) {
                int m = m0 + r;
                float2 ad = dwt_scalar_eo(a2e, a2o, N2, m);
                pd3[m] = ad.y;
                if (m & 1) a3o[m >> 1] = ad.x; else a3e[m >> 1] = ad.x;
            }
        }
    }
    {   // tail m = 2048..2060
        int m = 2048 + tid;
        if (m < N3) {
            float2 ad = dwt_scalar_eo(a2e, a2o, N2, m);
            pd3[m] = ad.y;
            if (m & 1) a3o[m >> 1] = ad.x; else a3e[m >> 1] = ad.x;
        }
    }
    __syncthreads();

    // ---- level 4: smem split a3 -> a4/d4 global (normal layout) ----
    {
        int m0 = 4 * tid;                  // < 1024
        if (m0 >= 8) {
            float e[12], o[12];
            #pragma unroll
            for (int j = 0; j < 3; j++) {
                float4 ve = *reinterpret_cast<const float4*>(a3e + m0 - 8 + 4 * j);
                float4 vo = *reinterpret_cast<const float4*>(a3o + m0 - 8 + 4 * j);
                e[4*j]=ve.x; e[4*j+1]=ve.y; e[4*j+2]=ve.z; e[4*j+3]=ve.w;
                o[4*j]=vo.x; o[4*j+1]=vo.y; o[4*j+2]=vo.z; o[4*j+3]=vo.w;
            }
            float ca[4], cd[4];
            dwt4_eo<1>(e, o, ca, cd);
            *reinterpret_cast<float4*>(pa4 + m0) = make_float4(ca[0], ca[1], ca[2], ca[3]);
            *reinterpret_cast<float4*>(pd4 + m0) = make_float4(cd[0], cd[1], cd[2], cd[3]);
        } else {
            #pragma unroll
            for (int r = 0; r < 4; r++) {
                int m = m0 + r;
                float2 ad = dwt_scalar_eo(a3e, a3o, N3, m);
                pa4[m] = ad.x; pd4[m] = ad.y;
            }
        }
        int m = 1024 + tid;                // tail m = 1024..1037
        if (m < N4) {
            float2 ad = dwt_scalar_eo(a3e, a3o, N3, m);
            pa4[m] = ad.x; pd4[m] = ad.y;
        }
    }
}

// ---------- idwt core ----------
__device__ __forceinline__ void idwt4(const float* a, const float* d, float* o) {
    const float H[16] = HLIT;
    #pragma unroll
    for (int pp = 0; pp < 4; pp++) {
        float e = 0.f, od = 0.f;
        #pragma unroll
        for (int s = 0; s < 8; s++) {
            e  = fmaf(H[14 - 2 * s], a[pp + s], e);
            e  = fmaf(H[2 * s + 1],  d[pp + s], e);
            od = fmaf(H[15 - 2 * s], a[pp + s], od);
            od = fmaf(-H[2 * s],     d[pp + s], od);
        }
        o[2*pp] = e; o[2*pp+1] = od;
    }
}

__device__ __forceinline__ void idwt_pass(const float* __restrict__ ca,
                                          const float* __restrict__ cd,
                                          int n, float thr,
                                          float* __restrict__ rec, int tid)
{
    int plim = n - 7;
    for (int p0 = 4 * tid; p0 < plim; p0 += 1024) {
        float a[12], d[12];
        if (p0 + 12 <= n) {
            #pragma unroll
            for (int j = 0; j < 3; j++) {
                float4 va = *reinterpret_cast<const float4*>(ca + p0 + 4 * j);
                float4 vd = *reinterpret_cast<const float4*>(cd + p0 + 4 * j);
                a[4*j] = va.x; a[4*j+1] = va.y; a[4*j+2] = va.z; a[4*j+3] = va.w;
                d[4*j] = vd.x; d[4*j+1] = vd.y; d[4*j+2] = vd.z; d[4*j+3] = vd.w;
            }
        } else {
            #pragma unroll
            for (int j = 0; j < 12; j++) {
                int q = p0 + j; if (q > n - 1) q = n - 1;
                a[j] = ca[q]; d[j] = cd[q];
            }
        }
        #pragma unroll
        for (int j = 0; j < 12; j++) d[j] = softthr(d[j], thr);
        float o[8];
        idwt4(a, d, o);
        if (p0 + 4 <= plim) {
            *reinterpret_cast<float4*>(rec + 2 * p0)     = make_float4(o[0], o[1], o[2], o[3]);
            *reinterpret_cast<float4*>(rec + 2 * p0 + 4) = make_float4(o[4], o[5], o[6], o[7]);
        } else {
            #pragma unroll
            for (int pp = 0; pp < 4; pp++)
                if (p0 + pp < plim) {
                    rec[2 * (p0 + pp)]     = o[2*pp];
                    rec[2 * (p0 + pp) + 1] = o[2*pp+1];
                }
        }
    }
}

// ============ K4: IDWT 4 -> 3 -> 2 -> 1, final level streams to out =======
#define SM_FLOATS 12320
#define SM_BYTES  (SM_FLOATS * 4)
#define OFF_HI    8208

__global__ void __launch_bounds__(256, 4)
k_inv(const float* __restrict__ a4g, const float* __restrict__ d4g,
      const float* __restrict__ d3g, const float* __restrict__ d2g,
      const float* __restrict__ d1g, const float* __restrict__ thr_arr,
      float* __restrict__ out)
{
    extern __shared__ float sm[];
    float* REC = sm;             // flat 8200
    float* R4  = sm;             // overlays REC
    float* R3  = sm + OFF_HI;    // flat 4108

    const int tid = threadIdx.x;
    const int row = blockIdx.x;
    const float thr = __ldg(thr_arr + row);
    const float* pa4 = a4g + (size_t)row * S4;
    const float* pd4 = d4g + (size_t)row * S4;
    const float* pd3 = d3g + (size_t)row * S3;
    const float* pd2 = d2g + (size_t)row * S2;
    const float* pd1 = d1g + (size_t)row * S1;
    float* orow = out + (size_t)row * LROW;

    idwt_pass(pa4, pd4, N4, thr, R4, tid);   __syncthreads();
    idwt_pass(R4,  pd3, N3, thr, R3, tid);   __syncthreads();
    idwt_pass(R3,  pd2, N2, thr, REC, tid);  __syncthreads();
    idwt_pass(REC, pd1, N1, thr, orow, tid);
}

extern "C" void kernel_launch(void* const* d_in, const int* in_sizes, int n_in,
                              void* d_out, int out_size)
{
    const float* x = (const float*)d_in[0];
    float* out = (float*)d_out;
    int rows = in_sizes[0] / LROW;   // 2048

    float *a1, *d1, *d2, *d3, *d4, *a4, *thr;
    cudaGetSymbolAddress((void**)&a1, g_a1);
    cudaGetSymbolAddress((void**)&d1, g_d1);
    cudaGetSymbolAddress((void**)&d2, g_d2);
    cudaGetSymbolAddress((void**)&d3, g_d3);
    cudaGetSymbolAddress((void**)&d4, g_d4);
    cudaGetSymbolAddress((void**)&a4, g_a4);
    cudaGetSymbolAddress((void**)&thr, g_thr);

    cudaFuncSetAttribute(k_inv, cudaFuncAttributeMaxDynamicSharedMemorySize, SM_BYTES);

    k_dwt1  <<<dim3(4, rows), 256>>>(x, a1, d1);
    k_med   <<<rows, 256>>>(d1, thr);          // independent of k_dwt234
    k_dwt234<<<rows, 256>>>(a1, d2, d3, d4, a4);
    k_inv   <<<rows, 256, SM_BYTES>>>(a4, d4, d3, d2, d1, thr, out);
}